// round 16
// baseline (speedup 1.0000x reference)
#include <cuda_runtime.h>
#include <cuda_bf16.h>
#include <cuda_fp16.h>
#include <cstdint>

#define N_NODES 50000
#define N_EDGES 800000
#define IN_DIM 256
#define OUT_DIM 64

// Scratch: H stored as fp16 (half2 pairs), 128 B per node row.
__device__ uint2  g_Hh[(N_NODES + 128) * 16];   // [node][q] = 4 cols as 2x half2
__device__ int    g_deg[N_NODES];
__device__ float  g_dinv[N_NODES];
__device__ int    g_rowptr[N_NODES];
__device__ int    g_cursor[N_NODES];
__device__ int    g_esrc[N_EDGES];
__device__ int    g_ctr;

// ---------------------------------------------------------------------------
// degree histogram over dst (g_deg zeroed via memset; thread 0 zeroes g_ctr)
__global__ void k_count_deg(const int* __restrict__ dst, int e) {
    int i = blockIdx.x * blockDim.x + threadIdx.x;
    if (i == 0) g_ctr = 0;
    if (i < e) atomicAdd(&g_deg[dst[i]], 1);
}

// CSR slot allocation (order-free) + dinv
__global__ void k_alloc(int n) {
    int i = blockIdx.x * blockDim.x + threadIdx.x;
    int lane = threadIdx.x & 31;
    int d = (i < n) ? g_deg[i] : 0;
    int pre = d;
#pragma unroll
    for (int off = 1; off < 32; off <<= 1) {
        int x = __shfl_up_sync(0xFFFFFFFFu, pre, off);
        if (lane >= off) pre += x;
    }
    int ex  = pre - d;
    int tot = __shfl_sync(0xFFFFFFFFu, pre, 31);
    int base = 0;
    if (lane == 31) base = atomicAdd(&g_ctr, tot);
    base = __shfl_sync(0xFFFFFFFFu, base, 31);
    if (i < n) {
        int rp = base + ex;
        g_rowptr[i] = rp;
        g_cursor[i] = rp;
        g_dinv[i] = rsqrtf((float)d + 1.0f);
    }
}

// CSR fill
__global__ void k_fill(const int* __restrict__ src, const int* __restrict__ dst, int e) {
    int i = blockIdx.x * blockDim.x + threadIdx.x;
    if (i >= e) return;
    int d = dst[i];
    int pos = atomicAdd(&g_cursor[d], 1);
    g_esrc[pos] = src[i];
}

// ---------------------------------------------------------------------------
// mma.sync bf16 helpers (sm_80+ baseline PTX -> compiles for compute_100)
__device__ __forceinline__ uint32_t smem_u32(const void* p) {
    uint32_t a;
    asm("{ .reg .u64 t; cvta.to.shared.u64 t, %1; cvt.u32.u64 %0, t; }" : "=r"(a) : "l"(p));
    return a;
}
__device__ __forceinline__ void ldsm_x4(uint32_t addr, uint32_t& r0, uint32_t& r1,
                                        uint32_t& r2, uint32_t& r3) {
    asm volatile("ldmatrix.sync.aligned.m8n8.x4.shared.b16 {%0,%1,%2,%3}, [%4];"
                 : "=r"(r0), "=r"(r1), "=r"(r2), "=r"(r3) : "r"(addr));
}
__device__ __forceinline__ void mma_bf16(float* c, uint32_t a0, uint32_t a1, uint32_t a2,
                                         uint32_t a3, uint32_t b0, uint32_t b1) {
    asm volatile(
        "mma.sync.aligned.m16n8k16.row.col.f32.bf16.bf16.f32 "
        "{%0,%1,%2,%3}, {%4,%5,%6,%7}, {%8,%9}, {%0,%1,%2,%3};"
        : "+f"(c[0]), "+f"(c[1]), "+f"(c[2]), "+f"(c[3])
        : "r"(a0), "r"(a1), "r"(a2), "r"(a3), "r"(b0), "r"(b1));
}
// Dekker-style bf16 split of two floats -> packed hi pair + lo pair (a in low half)
__device__ __forceinline__ void bf16split2(float a, float b, uint32_t& hi, uint32_t& lo) {
    asm("cvt.rn.satfinite.bf16x2.f32 %0, %1, %2;" : "=r"(hi) : "f"(b), "f"(a));
    float ha = __uint_as_float(hi << 16);
    float hb = __uint_as_float(hi & 0xFFFF0000u);
    float ra = a - ha;
    float rb = b - hb;
    asm("cvt.rn.satfinite.bf16x2.f32 %0, %1, %2;" : "=r"(lo) : "f"(rb), "f"(ra));
}

// smem geometry: padded rows of 72 bf16 (144 B) -> ldmatrix conflict-free
// CTA tile: 128 rows x 64 cols, K chunked by 64. 256 threads = 8 warps.
#define KCH 64
#define PADK 72
#define SM_BIAS 0
#define SM_XH 256
#define SM_XL (SM_XH + 128 * PADK * 2)        // +18432
#define SM_WH (SM_XL + 128 * PADK * 2)        // +18432
#define SM_WL (SM_WH + 64 * PADK * 2)         // +9216
#define SM_MMA_TOTAL (SM_WL + 64 * PADK * 2)  // 55552

// ---------------------------------------------------------------------------
// Tensor-core GEMM: H = X @ W^T + b, stored as fp16 for the gather.
// 3-pass bf16 split: D = Xh*Wh + Xh*Wl + Xl*Wh (fp32 accumulate).
// Software-pipelined: chunk k+1's global loads overlap chunk k's mma stage.
__global__ __launch_bounds__(256) void k_gemm_mma(const float* __restrict__ X,
                                                  const float* __restrict__ W,
                                                  const float* __restrict__ b, int n) {
    extern __shared__ char smem[];
    uint32_t sb = smem_u32(smem);
    int tid = threadIdx.x;
    int wid = tid >> 5;
    int lane = tid & 31;
    int nodeBase = blockIdx.x * 128;
    int warpRow = wid * 16;

    if (tid < 64) ((float*)(smem + SM_BIAS))[tid] = b[tid];

    float acc[8][4];
#pragma unroll
    for (int t = 0; t < 8; t++)
#pragma unroll
        for (int j = 0; j < 4; j++) acc[t][j] = 0.0f;

    // global-load assignments (fixed per thread across chunks)
    int xrow = tid >> 1;
    int xkh = (tid & 1) * 32;
    int grow = nodeBase + xrow;
    bool ok = grow < n;
    const float4* xptr = (const float4*)(X + (long long)grow * IN_DIM + xkh);
    int wrow = tid >> 2;
    int wkq = (tid & 3) * 16;
    const float4* wptr = (const float4*)(W + (long long)wrow * IN_DIM + wkq);

    const float4 z4 = make_float4(0.f, 0.f, 0.f, 0.f);
    float4 xreg[8], wreg[4];
    // preload chunk 0
#pragma unroll
    for (int j = 0; j < 8; j++) xreg[j] = ok ? xptr[j] : z4;
#pragma unroll
    for (int j = 0; j < 4; j++) wreg[j] = wptr[j];

    uint32_t* XH = (uint32_t*)(smem + SM_XH);
    uint32_t* XL = (uint32_t*)(smem + SM_XL);
    uint32_t* WH = (uint32_t*)(smem + SM_WH);
    uint32_t* WL = (uint32_t*)(smem + SM_WL);
    int xbase = xrow * (PADK / 2) + (xkh >> 1);
    int wbase = wrow * (PADK / 2) + (wkq >> 1);

    for (int kc = 0; kc < IN_DIM / KCH; kc++) {
        // convert + store current chunk from regs
#pragma unroll
        for (int j = 0; j < 8; j++) {
            uint2 hi, lo;
            bf16split2(xreg[j].x, xreg[j].y, hi.x, lo.x);
            bf16split2(xreg[j].z, xreg[j].w, hi.y, lo.y);
            *(uint2*)&XH[xbase + j * 2] = hi;
            *(uint2*)&XL[xbase + j * 2] = lo;
        }
#pragma unroll
        for (int j = 0; j < 4; j++) {
            uint2 hi, lo;
            bf16split2(wreg[j].x, wreg[j].y, hi.x, lo.x);
            bf16split2(wreg[j].z, wreg[j].w, hi.y, lo.y);
            *(uint2*)&WH[wbase + j * 2] = hi;
            *(uint2*)&WL[wbase + j * 2] = lo;
        }
        __syncthreads();

        // prefetch next chunk (LDG latency hides under the mma stage below)
        if (kc < IN_DIM / KCH - 1) {
            const float4* xp = xptr + (kc + 1) * (KCH / 4);
            const float4* wp = wptr + (kc + 1) * (KCH / 4);
#pragma unroll
            for (int j = 0; j < 8; j++) xreg[j] = ok ? xp[j] : z4;
#pragma unroll
            for (int j = 0; j < 4; j++) wreg[j] = wp[j];
        }

#pragma unroll
        for (int ks = 0; ks < KCH / 16; ks++) {
            // A fragments (16x16): lanes 0-15 rows, lanes>=16 second 16B k-chunk
            uint32_t aAddr = sb + (uint32_t)((warpRow + (lane & 15)) * (PADK * 2)
                                             + ks * 32 + (lane >> 4) * 16);
            uint32_t ah[4], al[4];
            ldsm_x4(aAddr + SM_XH, ah[0], ah[1], ah[2], ah[3]);
            ldsm_x4(aAddr + SM_XL, al[0], al[1], al[2], al[3]);
#pragma unroll
            for (int ntp = 0; ntp < 4; ntp++) {
                int m = lane >> 3;  // matrix index 0..3
                uint32_t bAddr = sb + (uint32_t)((ntp * 16 + (m >> 1) * 8 + (lane & 7)) * (PADK * 2)
                                                 + ks * 32 + (m & 1) * 16);
                uint32_t bh[4], bl[4];
                ldsm_x4(bAddr + SM_WH, bh[0], bh[1], bh[2], bh[3]);
                ldsm_x4(bAddr + SM_WL, bl[0], bl[1], bl[2], bl[3]);
                float* c0 = acc[ntp * 2 + 0];
                float* c1 = acc[ntp * 2 + 1];
                mma_bf16(c0, ah[0], ah[1], ah[2], ah[3], bh[0], bh[1]);
                mma_bf16(c0, ah[0], ah[1], ah[2], ah[3], bl[0], bl[1]);
                mma_bf16(c0, al[0], al[1], al[2], al[3], bh[0], bh[1]);
                mma_bf16(c1, ah[0], ah[1], ah[2], ah[3], bh[2], bh[3]);
                mma_bf16(c1, ah[0], ah[1], ah[2], ah[3], bl[2], bl[3]);
                mma_bf16(c1, al[0], al[1], al[2], al[3], bh[2], bh[3]);
            }
        }
        __syncthreads();
    }

    // epilogue: write fp16 H. c0,c1 -> row gr, cols col..col+1; c2,c3 -> row gr+8
    const float* bs = (const float*)(smem + SM_BIAS);
    __half2* Hh2 = (__half2*)g_Hh;    // index: row*32 + col/2
    int gr = lane >> 2;
    int gc = (lane & 3) * 2;
    int row0 = nodeBase + warpRow + gr;
    int row1 = row0 + 8;
#pragma unroll
    for (int nt = 0; nt < 8; nt++) {
        int col = nt * 8 + gc;
        float b0 = bs[col], b1 = bs[col + 1];
        if (row0 < n)
            Hh2[row0 * 32 + (col >> 1)] = __floats2half2_rn(acc[nt][0] + b0, acc[nt][1] + b1);
        if (row1 < n)
            Hh2[row1 * 32 + (col >> 1)] = __floats2half2_rn(acc[nt][2] + b0, acc[nt][3] + b1);
    }
}

// ---------------------------------------------------------------------------
// threefry: JAX partitionable 32-bit path: bits = out0 ^ out1, counter (0, i)
__device__ __forceinline__ uint32_t threefry_xor(uint32_t c0, uint32_t c1) {
    const uint32_t k0 = 0u, k1 = 42u;
    const uint32_t k2 = k0 ^ k1 ^ 0x1BD11BDAu;
    uint32_t x0 = c0 + k0;
    uint32_t x1 = c1 + k1;
#define TF_RND(r) { x0 += x1; x1 = (x1 << (r)) | (x1 >> (32 - (r))); x1 ^= x0; }
    TF_RND(13) TF_RND(15) TF_RND(26) TF_RND(6)
    x0 += k1; x1 += k2 + 1u;
    TF_RND(17) TF_RND(29) TF_RND(16) TF_RND(24)
    x0 += k2; x1 += k0 + 2u;
    TF_RND(13) TF_RND(15) TF_RND(26) TF_RND(6)
    x0 += k0; x1 += k1 + 3u;
    TF_RND(17) TF_RND(29) TF_RND(16) TF_RND(24)
    x0 += k1; x1 += k2 + 4u;
    TF_RND(13) TF_RND(15) TF_RND(26) TF_RND(6)
    x0 += k2; x1 += k0 + 5u;
#undef TF_RND
    return x0 ^ x1;
}

__device__ __forceinline__ void acc_h(float4& acc, uint2 raw, float w) {
    float2 f0 = __half22float2(*(__half2*)&raw.x);
    float2 f1 = __half22float2(*(__half2*)&raw.y);
    acc.x += f0.x * w;
    acc.y += f0.y * w;
    acc.z += f1.x * w;
    acc.w += f1.y * w;
}

// ---------------------------------------------------------------------------
// Gather + self-loop + normalization + ReLU + dropout, fully fused.
// 16 threads per node, 4 cols (one uint2 = 2x half2) each. fp16 H halves
// the dominant L2 traffic. 8-deep unroll, 4-deep mid-tail, singles.
__global__ __launch_bounds__(256) void k_gather(float* __restrict__ out, int n) {
    int t = blockIdx.x * blockDim.x + threadIdx.x;
    int node = t >> 4;
    int q = t & 15;
    if (node >= n) return;

    const uint2* Hh = g_Hh;
    int beg = g_rowptr[node];
    int cnt = g_deg[node];
    int end = beg + cnt;
    float dv = g_dinv[node];

    float4 acc = make_float4(0.f, 0.f, 0.f, 0.f);
    acc_h(acc, Hh[node * 16 + q], dv);   // self term

    int j = beg;
    for (; j + 8 <= end; j += 8) {
        int s[8];
#pragma unroll
        for (int u = 0; u < 8; u++) s[u] = g_esrc[j + u];
        float w[8];
#pragma unroll
        for (int u = 0; u < 8; u++) w[u] = g_dinv[s[u]];
        uint2 a[8];
#pragma unroll
        for (int u = 0; u < 8; u++) a[u] = Hh[s[u] * 16 + q];
#pragma unroll
        for (int u = 0; u < 8; u++) acc_h(acc, a[u], w[u]);
    }
    if (j + 4 <= end) {
        int s0 = g_esrc[j + 0];
        int s1 = g_esrc[j + 1];
        int s2 = g_esrc[j + 2];
        int s3 = g_esrc[j + 3];
        float w0 = g_dinv[s0];
        float w1 = g_dinv[s1];
        float w2 = g_dinv[s2];
        float w3 = g_dinv[s3];
        uint2 a0 = Hh[s0 * 16 + q];
        uint2 a1 = Hh[s1 * 16 + q];
        uint2 a2 = Hh[s2 * 16 + q];
        uint2 a3 = Hh[s3 * 16 + q];
        acc_h(acc, a0, w0);
        acc_h(acc, a1, w1);
        acc_h(acc, a2, w2);
        acc_h(acc, a3, w3);
        j += 4;
    }
    for (; j < end; j++) {
        int s = g_esrc[j];
        acc_h(acc, Hh[s * 16 + q], g_dinv[s]);
    }

    acc.x *= dv; acc.y *= dv; acc.z *= dv; acc.w *= dv;

    uint32_t base = (uint32_t)(node * OUT_DIM + q * 4);
    uint32_t r0 = threefry_xor(0u, base + 0u);
    uint32_t r1 = threefry_xor(0u, base + 1u);
    uint32_t r2 = threefry_xor(0u, base + 2u);
    uint32_t r3 = threefry_xor(0u, base + 3u);
    float4 o;
    o.x = (r0 & 0x80000000u) ? 0.0f : 2.0f * fmaxf(acc.x, 0.0f);
    o.y = (r1 & 0x80000000u) ? 0.0f : 2.0f * fmaxf(acc.y, 0.0f);
    o.z = (r2 & 0x80000000u) ? 0.0f : 2.0f * fmaxf(acc.z, 0.0f);
    o.w = (r3 & 0x80000000u) ? 0.0f : 2.0f * fmaxf(acc.w, 0.0f);
    ((float4*)out)[node * 16 + q] = o;
}

// ---------------------------------------------------------------------------
extern "C" void kernel_launch(void* const* d_in, const int* in_sizes, int n_in,
                              void* d_out, int out_size) {
    const float* X  = (const float*)d_in[0];
    const float* W  = (const float*)d_in[1];
    const float* b  = (const float*)d_in[2];
    const int* src  = (const int*)d_in[3];
    const int* dst  = (const int*)d_in[4];
    float* out = (float*)d_out;

    int n = in_sizes[0] / IN_DIM;   // 50000
    int e = in_sizes[3];            // 800000

    void* degPtr = nullptr;
    cudaGetSymbolAddress(&degPtr, g_deg);

    static cudaStream_t s2 = nullptr;
    static cudaEvent_t evFork = nullptr, evJoin = nullptr;
    static bool tried = false;
    if (!tried) {
        tried = true;
        cudaFuncSetAttribute(k_gemm_mma, cudaFuncAttributeMaxDynamicSharedMemorySize,
                             SM_MMA_TOTAL);
        if (cudaStreamCreateWithFlags(&s2, cudaStreamNonBlocking) != cudaSuccess) s2 = nullptr;
        if (s2) {
            if (cudaEventCreateWithFlags(&evFork, cudaEventDisableTiming) != cudaSuccess ||
                cudaEventCreateWithFlags(&evJoin, cudaEventDisableTiming) != cudaSuccess) {
                s2 = nullptr;
            }
        }
    }

    int gemm_grid = (n + 127) / 128;
    int gather_blocks = (n * 16 + 255) / 256;

    if (s2) {
        cudaEventRecord(evFork, 0);
        cudaStreamWaitEvent(s2, evFork, 0);

        cudaMemsetAsync(degPtr, 0, n * sizeof(int), s2);
        k_count_deg<<<(e + 255) / 256, 256, 0, s2>>>(dst, e);
        k_alloc<<<(n + 255) / 256, 256, 0, s2>>>(n);
        k_fill<<<(e + 255) / 256, 256, 0, s2>>>(src, dst, e);
        cudaEventRecord(evJoin, s2);

        k_gemm_mma<<<gemm_grid, 256, SM_MMA_TOTAL>>>(X, W, b, n);

        cudaStreamWaitEvent(0, evJoin, 0);
        k_gather<<<gather_blocks, 256>>>(out, n);
    } else {
        cudaMemsetAsync(degPtr, 0, n * sizeof(int));
        k_count_deg<<<(e + 255) / 256, 256>>>(dst, e);
        k_alloc<<<(n + 255) / 256, 256>>>(n);
        k_fill<<<(e + 255) / 256, 256>>>(src, dst, e);
        k_gemm_mma<<<gemm_grid, 256, SM_MMA_TOTAL>>>(X, W, b, n);
        k_gather<<<gather_blocks, 256>>>(out, n);
    }
}

// round 17
// speedup vs baseline: 1.0210x; 1.0210x over previous
#include <cuda_runtime.h>
#include <cuda_bf16.h>
#include <cuda_fp16.h>
#include <cstdint>

#define N_NODES 50000
#define N_EDGES 800000
#define IN_DIM 256
#define OUT_DIM 64

// Scratch: H stored as fp16 (half2 pairs), 128 B per node row.
__device__ uint2  g_Hh[(N_NODES + 128) * 16];   // [node][q] = 4 cols as 2x half2
__device__ int    g_deg[N_NODES];
__device__ float  g_dinv[N_NODES];
__device__ int    g_rowptr[N_NODES];
__device__ int    g_cursor[N_NODES];
__device__ int    g_esrc[N_EDGES + 8];   // +8 zero padding: predicated groups read past end
__device__ int    g_ctr;

// ---------------------------------------------------------------------------
// degree histogram over dst (g_deg zeroed via memset; thread 0 zeroes g_ctr)
__global__ void k_count_deg(const int* __restrict__ dst, int e) {
    int i = blockIdx.x * blockDim.x + threadIdx.x;
    if (i == 0) g_ctr = 0;
    if (i < e) atomicAdd(&g_deg[dst[i]], 1);
}

// CSR slot allocation (order-free) + dinv
__global__ void k_alloc(int n) {
    int i = blockIdx.x * blockDim.x + threadIdx.x;
    int lane = threadIdx.x & 31;
    int d = (i < n) ? g_deg[i] : 0;
    int pre = d;
#pragma unroll
    for (int off = 1; off < 32; off <<= 1) {
        int x = __shfl_up_sync(0xFFFFFFFFu, pre, off);
        if (lane >= off) pre += x;
    }
    int ex  = pre - d;
    int tot = __shfl_sync(0xFFFFFFFFu, pre, 31);
    int base = 0;
    if (lane == 31) base = atomicAdd(&g_ctr, tot);
    base = __shfl_sync(0xFFFFFFFFu, base, 31);
    if (i < n) {
        int rp = base + ex;
        g_rowptr[i] = rp;
        g_cursor[i] = rp;
        g_dinv[i] = rsqrtf((float)d + 1.0f);
    }
}

// CSR fill
__global__ void k_fill(const int* __restrict__ src, const int* __restrict__ dst, int e) {
    int i = blockIdx.x * blockDim.x + threadIdx.x;
    if (i >= e) return;
    int d = dst[i];
    int pos = atomicAdd(&g_cursor[d], 1);
    g_esrc[pos] = src[i];
}

// ---------------------------------------------------------------------------
// mma.sync bf16 helpers (sm_80+ baseline PTX -> compiles for compute_100)
__device__ __forceinline__ uint32_t smem_u32(const void* p) {
    uint32_t a;
    asm("{ .reg .u64 t; cvta.to.shared.u64 t, %1; cvt.u32.u64 %0, t; }" : "=r"(a) : "l"(p));
    return a;
}
__device__ __forceinline__ void ldsm_x4(uint32_t addr, uint32_t& r0, uint32_t& r1,
                                        uint32_t& r2, uint32_t& r3) {
    asm volatile("ldmatrix.sync.aligned.m8n8.x4.shared.b16 {%0,%1,%2,%3}, [%4];"
                 : "=r"(r0), "=r"(r1), "=r"(r2), "=r"(r3) : "r"(addr));
}
__device__ __forceinline__ void mma_bf16(float* c, uint32_t a0, uint32_t a1, uint32_t a2,
                                         uint32_t a3, uint32_t b0, uint32_t b1) {
    asm volatile(
        "mma.sync.aligned.m16n8k16.row.col.f32.bf16.bf16.f32 "
        "{%0,%1,%2,%3}, {%4,%5,%6,%7}, {%8,%9}, {%0,%1,%2,%3};"
        : "+f"(c[0]), "+f"(c[1]), "+f"(c[2]), "+f"(c[3])
        : "r"(a0), "r"(a1), "r"(a2), "r"(a3), "r"(b0), "r"(b1));
}
// Dekker-style bf16 split of two floats -> packed hi pair + lo pair (a in low half)
__device__ __forceinline__ void bf16split2(float a, float b, uint32_t& hi, uint32_t& lo) {
    asm("cvt.rn.satfinite.bf16x2.f32 %0, %1, %2;" : "=r"(hi) : "f"(b), "f"(a));
    float ha = __uint_as_float(hi << 16);
    float hb = __uint_as_float(hi & 0xFFFF0000u);
    float ra = a - ha;
    float rb = b - hb;
    asm("cvt.rn.satfinite.bf16x2.f32 %0, %1, %2;" : "=r"(lo) : "f"(rb), "f"(ra));
}

// smem geometry: padded rows of 72 bf16 (144 B) -> ldmatrix conflict-free
// CTA tile: 128 rows x 64 cols, K chunked by 64. 256 threads = 8 warps.
#define KCH 64
#define PADK 72
#define SM_BIAS 0
#define SM_XH 256
#define SM_XL (SM_XH + 128 * PADK * 2)        // +18432
#define SM_WH (SM_XL + 128 * PADK * 2)        // +18432
#define SM_WL (SM_WH + 64 * PADK * 2)         // +9216
#define SM_MMA_TOTAL (SM_WL + 64 * PADK * 2)  // 55552

// ---------------------------------------------------------------------------
// Tensor-core GEMM: H = X @ W^T + b, stored as fp16 for the gather.
// 3-pass bf16 split: D = Xh*Wh + Xh*Wl + Xl*Wh (fp32 accumulate).
// Software-pipelined: chunk k+1's global loads overlap chunk k's mma stage.
__global__ __launch_bounds__(256) void k_gemm_mma(const float* __restrict__ X,
                                                  const float* __restrict__ W,
                                                  const float* __restrict__ b, int n) {
    extern __shared__ char smem[];
    uint32_t sb = smem_u32(smem);
    int tid = threadIdx.x;
    int wid = tid >> 5;
    int lane = tid & 31;
    int nodeBase = blockIdx.x * 128;
    int warpRow = wid * 16;

    if (tid < 64) ((float*)(smem + SM_BIAS))[tid] = b[tid];

    float acc[8][4];
#pragma unroll
    for (int t = 0; t < 8; t++)
#pragma unroll
        for (int j = 0; j < 4; j++) acc[t][j] = 0.0f;

    // global-load assignments (fixed per thread across chunks)
    int xrow = tid >> 1;
    int xkh = (tid & 1) * 32;
    int grow = nodeBase + xrow;
    bool ok = grow < n;
    const float4* xptr = (const float4*)(X + (long long)grow * IN_DIM + xkh);
    int wrow = tid >> 2;
    int wkq = (tid & 3) * 16;
    const float4* wptr = (const float4*)(W + (long long)wrow * IN_DIM + wkq);

    const float4 z4 = make_float4(0.f, 0.f, 0.f, 0.f);
    float4 xreg[8], wreg[4];
    // preload chunk 0
#pragma unroll
    for (int j = 0; j < 8; j++) xreg[j] = ok ? xptr[j] : z4;
#pragma unroll
    for (int j = 0; j < 4; j++) wreg[j] = wptr[j];

    uint32_t* XH = (uint32_t*)(smem + SM_XH);
    uint32_t* XL = (uint32_t*)(smem + SM_XL);
    uint32_t* WH = (uint32_t*)(smem + SM_WH);
    uint32_t* WL = (uint32_t*)(smem + SM_WL);
    int xbase = xrow * (PADK / 2) + (xkh >> 1);
    int wbase = wrow * (PADK / 2) + (wkq >> 1);

    for (int kc = 0; kc < IN_DIM / KCH; kc++) {
        // convert + store current chunk from regs
#pragma unroll
        for (int j = 0; j < 8; j++) {
            uint2 hi, lo;
            bf16split2(xreg[j].x, xreg[j].y, hi.x, lo.x);
            bf16split2(xreg[j].z, xreg[j].w, hi.y, lo.y);
            *(uint2*)&XH[xbase + j * 2] = hi;
            *(uint2*)&XL[xbase + j * 2] = lo;
        }
#pragma unroll
        for (int j = 0; j < 4; j++) {
            uint2 hi, lo;
            bf16split2(wreg[j].x, wreg[j].y, hi.x, lo.x);
            bf16split2(wreg[j].z, wreg[j].w, hi.y, lo.y);
            *(uint2*)&WH[wbase + j * 2] = hi;
            *(uint2*)&WL[wbase + j * 2] = lo;
        }
        __syncthreads();

        // prefetch next chunk (LDG latency hides under the mma stage below)
        if (kc < IN_DIM / KCH - 1) {
            const float4* xp = xptr + (kc + 1) * (KCH / 4);
            const float4* wp = wptr + (kc + 1) * (KCH / 4);
#pragma unroll
            for (int j = 0; j < 8; j++) xreg[j] = ok ? xp[j] : z4;
#pragma unroll
            for (int j = 0; j < 4; j++) wreg[j] = wp[j];
        }

#pragma unroll
        for (int ks = 0; ks < KCH / 16; ks++) {
            // A fragments (16x16): lanes 0-15 rows, lanes>=16 second 16B k-chunk
            uint32_t aAddr = sb + (uint32_t)((warpRow + (lane & 15)) * (PADK * 2)
                                             + ks * 32 + (lane >> 4) * 16);
            uint32_t ah[4], al[4];
            ldsm_x4(aAddr + SM_XH, ah[0], ah[1], ah[2], ah[3]);
            ldsm_x4(aAddr + SM_XL, al[0], al[1], al[2], al[3]);
#pragma unroll
            for (int ntp = 0; ntp < 4; ntp++) {
                int m = lane >> 3;  // matrix index 0..3
                uint32_t bAddr = sb + (uint32_t)((ntp * 16 + (m >> 1) * 8 + (lane & 7)) * (PADK * 2)
                                                 + ks * 32 + (m & 1) * 16);
                uint32_t bh[4], bl[4];
                ldsm_x4(bAddr + SM_WH, bh[0], bh[1], bh[2], bh[3]);
                ldsm_x4(bAddr + SM_WL, bl[0], bl[1], bl[2], bl[3]);
                float* c0 = acc[ntp * 2 + 0];
                float* c1 = acc[ntp * 2 + 1];
                mma_bf16(c0, ah[0], ah[1], ah[2], ah[3], bh[0], bh[1]);
                mma_bf16(c0, ah[0], ah[1], ah[2], ah[3], bl[0], bl[1]);
                mma_bf16(c0, al[0], al[1], al[2], al[3], bh[0], bh[1]);
                mma_bf16(c1, ah[0], ah[1], ah[2], ah[3], bh[2], bh[3]);
                mma_bf16(c1, ah[0], ah[1], ah[2], ah[3], bl[2], bl[3]);
                mma_bf16(c1, al[0], al[1], al[2], al[3], bh[2], bh[3]);
            }
        }
        __syncthreads();
    }

    // epilogue: write fp16 H. c0,c1 -> row gr, cols col..col+1; c2,c3 -> row gr+8
    const float* bs = (const float*)(smem + SM_BIAS);
    __half2* Hh2 = (__half2*)g_Hh;    // index: row*32 + col/2
    int gr = lane >> 2;
    int gc = (lane & 3) * 2;
    int row0 = nodeBase + warpRow + gr;
    int row1 = row0 + 8;
#pragma unroll
    for (int nt = 0; nt < 8; nt++) {
        int col = nt * 8 + gc;
        float b0 = bs[col], b1 = bs[col + 1];
        if (row0 < n)
            Hh2[row0 * 32 + (col >> 1)] = __floats2half2_rn(acc[nt][0] + b0, acc[nt][1] + b1);
        if (row1 < n)
            Hh2[row1 * 32 + (col >> 1)] = __floats2half2_rn(acc[nt][2] + b0, acc[nt][3] + b1);
    }
}

// ---------------------------------------------------------------------------
// threefry: JAX partitionable 32-bit path: bits = out0 ^ out1, counter (0, i)
__device__ __forceinline__ uint32_t threefry_xor(uint32_t c0, uint32_t c1) {
    const uint32_t k0 = 0u, k1 = 42u;
    const uint32_t k2 = k0 ^ k1 ^ 0x1BD11BDAu;
    uint32_t x0 = c0 + k0;
    uint32_t x1 = c1 + k1;
#define TF_RND(r) { x0 += x1; x1 = (x1 << (r)) | (x1 >> (32 - (r))); x1 ^= x0; }
    TF_RND(13) TF_RND(15) TF_RND(26) TF_RND(6)
    x0 += k1; x1 += k2 + 1u;
    TF_RND(17) TF_RND(29) TF_RND(16) TF_RND(24)
    x0 += k2; x1 += k0 + 2u;
    TF_RND(13) TF_RND(15) TF_RND(26) TF_RND(6)
    x0 += k0; x1 += k1 + 3u;
    TF_RND(17) TF_RND(29) TF_RND(16) TF_RND(24)
    x0 += k1; x1 += k2 + 4u;
    TF_RND(13) TF_RND(15) TF_RND(26) TF_RND(6)
    x0 += k2; x1 += k0 + 5u;
#undef TF_RND
    return x0 ^ x1;
}

__device__ __forceinline__ void acc_h(float4& acc, uint2 raw, float w) {
    float2 f0 = __half22float2(*(__half2*)&raw.x);
    float2 f1 = __half22float2(*(__half2*)&raw.y);
    acc.x += f0.x * w;
    acc.y += f0.y * w;
    acc.z += f1.x * w;
    acc.w += f1.y * w;
}

// ---------------------------------------------------------------------------
// Gather + self-loop + normalization + ReLU + dropout, fully fused.
// 16 threads per node, 4 cols (one uint2 = 2x half2) each.
// NO TAIL: every node runs ceil(deg/8) fully predicated 8-wide groups.
// Out-of-range slots read padded g_esrc (=0, valid node) with weight 0.
__global__ __launch_bounds__(256) void k_gather(float* __restrict__ out, int n) {
    int t = blockIdx.x * blockDim.x + threadIdx.x;
    int node = t >> 4;
    int q = t & 15;
    if (node >= n) return;

    const uint2* Hh = g_Hh;
    int beg = g_rowptr[node];
    int cnt = g_deg[node];
    int end = beg + cnt;
    float dv = g_dinv[node];

    float4 acc = make_float4(0.f, 0.f, 0.f, 0.f);
    acc_h(acc, Hh[node * 16 + q], dv);   // self term

    for (int j = beg; j < end; j += 8) {
        int s[8];
#pragma unroll
        for (int u = 0; u < 8; u++) s[u] = g_esrc[j + u];      // padded: always safe
        float w[8];
#pragma unroll
        for (int u = 0; u < 8; u++)
            w[u] = (j + u < end) ? g_dinv[s[u]] : 0.0f;        // select, load unconditional
        uint2 a[8];
#pragma unroll
        for (int u = 0; u < 8; u++) a[u] = Hh[s[u] * 16 + q];  // full-MLP even in last group
#pragma unroll
        for (int u = 0; u < 8; u++) acc_h(acc, a[u], w[u]);
    }

    acc.x *= dv; acc.y *= dv; acc.z *= dv; acc.w *= dv;

    uint32_t base = (uint32_t)(node * OUT_DIM + q * 4);
    uint32_t r0 = threefry_xor(0u, base + 0u);
    uint32_t r1 = threefry_xor(0u, base + 1u);
    uint32_t r2 = threefry_xor(0u, base + 2u);
    uint32_t r3 = threefry_xor(0u, base + 3u);
    float4 o;
    o.x = (r0 & 0x80000000u) ? 0.0f : 2.0f * fmaxf(acc.x, 0.0f);
    o.y = (r1 & 0x80000000u) ? 0.0f : 2.0f * fmaxf(acc.y, 0.0f);
    o.z = (r2 & 0x80000000u) ? 0.0f : 2.0f * fmaxf(acc.z, 0.0f);
    o.w = (r3 & 0x80000000u) ? 0.0f : 2.0f * fmaxf(acc.w, 0.0f);
    ((float4*)out)[node * 16 + q] = o;
}

// ---------------------------------------------------------------------------
extern "C" void kernel_launch(void* const* d_in, const int* in_sizes, int n_in,
                              void* d_out, int out_size) {
    const float* X  = (const float*)d_in[0];
    const float* W  = (const float*)d_in[1];
    const float* b  = (const float*)d_in[2];
    const int* src  = (const int*)d_in[3];
    const int* dst  = (const int*)d_in[4];
    float* out = (float*)d_out;

    int n = in_sizes[0] / IN_DIM;   // 50000
    int e = in_sizes[3];            // 800000

    void* degPtr = nullptr;
    cudaGetSymbolAddress(&degPtr, g_deg);

    static cudaStream_t s2 = nullptr;
    static cudaEvent_t evFork = nullptr, evJoin = nullptr;
    static bool tried = false;
    if (!tried) {
        tried = true;
        cudaFuncSetAttribute(k_gemm_mma, cudaFuncAttributeMaxDynamicSharedMemorySize,
                             SM_MMA_TOTAL);
        if (cudaStreamCreateWithFlags(&s2, cudaStreamNonBlocking) != cudaSuccess) s2 = nullptr;
        if (s2) {
            if (cudaEventCreateWithFlags(&evFork, cudaEventDisableTiming) != cudaSuccess ||
                cudaEventCreateWithFlags(&evJoin, cudaEventDisableTiming) != cudaSuccess) {
                s2 = nullptr;
            }
        }
    }

    int gemm_grid = (n + 127) / 128;
    int gather_blocks = (n * 16 + 255) / 256;

    if (s2) {
        cudaEventRecord(evFork, 0);
        cudaStreamWaitEvent(s2, evFork, 0);

        cudaMemsetAsync(degPtr, 0, n * sizeof(int), s2);
        k_count_deg<<<(e + 255) / 256, 256, 0, s2>>>(dst, e);
        k_alloc<<<(n + 255) / 256, 256, 0, s2>>>(n);
        k_fill<<<(e + 255) / 256, 256, 0, s2>>>(src, dst, e);
        cudaEventRecord(evJoin, s2);

        k_gemm_mma<<<gemm_grid, 256, SM_MMA_TOTAL>>>(X, W, b, n);

        cudaStreamWaitEvent(0, evJoin, 0);
        k_gather<<<gather_blocks, 256>>>(out, n);
    } else {
        cudaMemsetAsync(degPtr, 0, n * sizeof(int));
        k_count_deg<<<(e + 255) / 256, 256>>>(dst, e);
        k_alloc<<<(n + 255) / 256, 256>>>(n);
        k_fill<<<(e + 255) / 256, 256>>>(src, dst, e);
        k_gemm_mma<<<gemm_grid, 256, SM_MMA_TOTAL>>>(X, W, b, n);
        k_gather<<<gather_blocks, 256>>>(out, n);
    }
}